// round 1
// baseline (speedup 1.0000x reference)
#include <cuda_runtime.h>
#include <math.h>

#define BB   64
#define NPG  1024
#define NN   (BB * NPG)       // 65536 nodes
#define EE   (BB * 16384)     // 1048576 edges
#define INF  64
#define HIDF 128
#define OUTF 32

#define ADJ_ELEMS  ((size_t)BB * NPG * NPG)   // 67108864
#define MEAN_OFF   ADJ_ELEMS
#define LS_OFF     (ADJ_ELEMS + (size_t)NN * OUTF)

// ---------------- scratch (static device globals; no runtime alloc) -------
__device__ int   g_cnt_out[NN];
__device__ int   g_cnt_in[NN];
__device__ float g_rs_out[NN];
__device__ float g_rs_in[NN];
__device__ int   g_rowptr[NN + 1];
__device__ int   g_bsum[64];
__device__ int   g_fill[NN];
__device__ int   g_csr[EE];
__device__ float g_h[NN * HIDF];   // layer-1 output (relu'd)
__device__ float g_p[NN * 64];     // (h * rs_out) @ [W2 | W3]
__device__ float g_z[NN * OUTF];   // latent z

// ---------------- f32x2 helpers (FFMA2) -----------------------------------
__device__ __forceinline__ unsigned long long pack2(float lo, float hi) {
    unsigned long long r;
    asm("mov.b64 %0, {%1, %2};" : "=l"(r) : "f"(lo), "f"(hi));
    return r;
}
__device__ __forceinline__ unsigned long long fma2(unsigned long long a,
                                                   unsigned long long b,
                                                   unsigned long long c) {
    unsigned long long d;
    asm("fma.rn.f32x2 %0, %1, %2, %3;" : "=l"(d) : "l"(a), "l"(b), "l"(c));
    return d;
}
__device__ __forceinline__ void unpack2(unsigned long long v, float& a, float& b) {
    asm("mov.b64 {%0, %1}, %2;" : "=f"(a), "=f"(b) : "l"(v));
}
__device__ __forceinline__ float sigm(float x) {
    return 1.0f / (1.0f + __expf(-x));
}

// ---------------- setup kernels -------------------------------------------
__global__ void k_zero() {
    int i = blockIdx.x * blockDim.x + threadIdx.x;
    if (i < NN) { g_cnt_out[i] = 0; g_cnt_in[i] = 0; g_fill[i] = 0; }
}

__global__ void k_count(const int* __restrict__ src, const int* __restrict__ dst) {
    int e = blockIdx.x * blockDim.x + threadIdx.x;
    if (e < EE) {
        atomicAdd(&g_cnt_out[src[e]], 1);
        atomicAdd(&g_cnt_in[dst[e]], 1);
    }
}

__global__ void k_rsqrt() {
    int i = blockIdx.x * blockDim.x + threadIdx.x;
    if (i < NN) {
        g_rs_out[i] = rsqrtf((float)max(g_cnt_out[i], 1));
        g_rs_in[i]  = rsqrtf((float)max(g_cnt_in[i], 1));
    }
}

// exclusive scan of g_cnt_in -> g_rowptr (2-level: 64 blocks x 1024)
__global__ void k_scan1() {
    __shared__ int sh[1024];
    int t = threadIdx.x;
    int i = blockIdx.x * 1024 + t;
    int v = g_cnt_in[i];
    sh[t] = v;
    __syncthreads();
    for (int ofs = 1; ofs < 1024; ofs <<= 1) {
        int x = (t >= ofs) ? sh[t - ofs] : 0;
        __syncthreads();
        sh[t] += x;
        __syncthreads();
    }
    g_rowptr[i] = sh[t] - v;            // exclusive within block
    if (t == 1023) g_bsum[blockIdx.x] = sh[t];
}

__global__ void k_scan2() {
    if (threadIdx.x == 0) {
        int s = 0;
        for (int i = 0; i < 64; i++) { int v = g_bsum[i]; g_bsum[i] = s; s += v; }
        g_rowptr[NN] = s;               // == EE
    }
}

__global__ void k_scan3() {
    int i = blockIdx.x * 1024 + threadIdx.x;
    g_rowptr[i] += g_bsum[blockIdx.x];
}

__global__ void k_csr(const int* __restrict__ src, const int* __restrict__ dst) {
    int e = blockIdx.x * blockDim.x + threadIdx.x;
    if (e < EE) {
        int d = dst[e];
        int pos = g_rowptr[d] + atomicAdd(&g_fill[d], 1);
        g_csr[pos] = src[e];
    }
}

// ---------------- layer 1: aggregate features + matmul W1 + relu ----------
// one warp per node; lane holds cols (lane, lane+32) of the 64-dim aggregate
__global__ __launch_bounds__(256) void k_layer1(const float* __restrict__ feat,
                                                const float* __restrict__ W1,
                                                const float* __restrict__ b1) {
    __shared__ __align__(16) float sW[INF * HIDF];   // [c][j], 32 KB
    __shared__ __align__(16) float sb[HIDF];
    int tid = threadIdx.x;
    for (int idx = tid; idx < INF * HIDF; idx += 256) sW[idx] = W1[idx];
    if (tid < HIDF) sb[tid] = b1[tid];
    __syncthreads();

    int warp = tid >> 5, lane = tid & 31;
    int n = blockIdx.x * 8 + warp;

    int beg = g_rowptr[n], end = g_rowptr[n + 1];
    float a0 = 0.f, a1 = 0.f;
    for (int e = beg; e < end; e++) {
        int s = g_csr[e];
        float rs = g_rs_out[s];
        const float* f = feat + s * INF;
        a0 = fmaf(f[lane], rs, a0);
        a1 = fmaf(f[lane + 32], rs, a1);
    }
    float rin = g_rs_in[n];
    a0 *= rin; a1 *= rin;

    float4 acc = *(const float4*)&sb[4 * lane];
#pragma unroll
    for (int c = 0; c < 32; c++) {
        float v = __shfl_sync(0xffffffffu, a0, c);
        float4 w = *(const float4*)&sW[c * HIDF + 4 * lane];
        acc.x = fmaf(v, w.x, acc.x); acc.y = fmaf(v, w.y, acc.y);
        acc.z = fmaf(v, w.z, acc.z); acc.w = fmaf(v, w.w, acc.w);
    }
#pragma unroll
    for (int c = 0; c < 32; c++) {
        float v = __shfl_sync(0xffffffffu, a1, c);
        float4 w = *(const float4*)&sW[(c + 32) * HIDF + 4 * lane];
        acc.x = fmaf(v, w.x, acc.x); acc.y = fmaf(v, w.y, acc.y);
        acc.z = fmaf(v, w.z, acc.z); acc.w = fmaf(v, w.w, acc.w);
    }
    acc.x = fmaxf(acc.x, 0.f); acc.y = fmaxf(acc.y, 0.f);
    acc.z = fmaxf(acc.z, 0.f); acc.w = fmaxf(acc.w, 0.f);
    *(float4*)&g_h[n * HIDF + 4 * lane] = acc;
}

// ---------------- p = (h * rs_out) @ [W2 | W3]  ([N,128] @ [128,64]) ------
__global__ __launch_bounds__(256) void k_p(const float* __restrict__ W2,
                                           const float* __restrict__ W3) {
    __shared__ __align__(16) float sW[HIDF * 64];    // [c][j], 32 KB
    int tid = threadIdx.x;
    for (int idx = tid; idx < HIDF * 64; idx += 256) {
        int c = idx >> 6, j = idx & 63;
        sW[idx] = (j < 32) ? W2[c * 32 + j] : W3[c * 32 + (j - 32)];
    }
    __syncthreads();

    int warp = tid >> 5, lane = tid & 31;
    int n = blockIdx.x * 8 + warp;

    float rs = g_rs_out[n];
    const float* h = g_h + n * HIDF;
    float h0 = h[lane] * rs, h1 = h[lane + 32] * rs;
    float h2 = h[lane + 64] * rs, h3 = h[lane + 96] * rs;

    float2 acc = make_float2(0.f, 0.f);
#pragma unroll
    for (int c = 0; c < 32; c++) {
        float v = __shfl_sync(0xffffffffu, h0, c);
        float2 w = *(const float2*)&sW[c * 64 + 2 * lane];
        acc.x = fmaf(v, w.x, acc.x); acc.y = fmaf(v, w.y, acc.y);
    }
#pragma unroll
    for (int c = 0; c < 32; c++) {
        float v = __shfl_sync(0xffffffffu, h1, c);
        float2 w = *(const float2*)&sW[(c + 32) * 64 + 2 * lane];
        acc.x = fmaf(v, w.x, acc.x); acc.y = fmaf(v, w.y, acc.y);
    }
#pragma unroll
    for (int c = 0; c < 32; c++) {
        float v = __shfl_sync(0xffffffffu, h2, c);
        float2 w = *(const float2*)&sW[(c + 64) * 64 + 2 * lane];
        acc.x = fmaf(v, w.x, acc.x); acc.y = fmaf(v, w.y, acc.y);
    }
#pragma unroll
    for (int c = 0; c < 32; c++) {
        float v = __shfl_sync(0xffffffffu, h3, c);
        float2 w = *(const float2*)&sW[(c + 96) * 64 + 2 * lane];
        acc.x = fmaf(v, w.x, acc.x); acc.y = fmaf(v, w.y, acc.y);
    }
    *(float2*)&g_p[n * 64 + 2 * lane] = acc;
}

// ---------------- aggregate p, add bias, z = mean + noise*exp(ls) ---------
__global__ __launch_bounds__(256) void k_agg2z(const float* __restrict__ noise,
                                               const float* __restrict__ b2,
                                               const float* __restrict__ b3,
                                               float* __restrict__ out_mean,
                                               float* __restrict__ out_ls) {
    int tid = threadIdx.x;
    int warp = tid >> 5, lane = tid & 31;
    int n = blockIdx.x * 8 + warp;

    int beg = g_rowptr[n], end = g_rowptr[n + 1];
    float a0 = 0.f, a1 = 0.f;
    for (int e = beg; e < end; e++) {
        int s = g_csr[e];
        const float* p = g_p + s * 64;
        a0 += p[lane];
        a1 += p[lane + 32];
    }
    float rin = g_rs_in[n];
    float mean = fmaf(a0, rin, b2[lane]);
    float ls   = fmaf(a1, rin, b3[lane]);
    float z    = fmaf(noise[n * OUTF + lane], __expf(ls), mean);
    out_mean[n * OUTF + lane] = mean;
    out_ls[n * OUTF + lane]   = ls;
    g_z[n * OUTF + lane]      = z;
}

// ---------------- adj = sigmoid(Z Z^T) per graph, 128x128 tiles -----------
// grid (8, 8, 64); block 256 (16x16); 8x8 outputs/thread via FFMA2 pairs
__global__ __launch_bounds__(256) void k_adj(float* __restrict__ out) {
    __shared__ __align__(16) float sAT[32 * 132];   // [k][r], pad 132
    __shared__ __align__(16) float sB[128 * 33];    // [j][k], pad 33

    int g  = blockIdx.z;
    int i0 = blockIdx.y * 128, j0 = blockIdx.x * 128;
    const float* zA = g_z + ((size_t)(g * NPG + i0)) * OUTF;
    const float* zBt = g_z + ((size_t)(g * NPG + j0)) * OUTF;
    int tid = threadIdx.x;

    for (int idx = tid; idx < 128 * 32; idx += 256) {
        int r = idx >> 5, k = idx & 31;
        float av = zA[idx];
        float bv = zBt[idx];
        sAT[k * 132 + r] = av;
        sB[r * 33 + k]   = bv;
    }
    __syncthreads();

    int tx = tid & 15, ty = tid >> 4;
    // rows: ty*8 + {0..7} as 4 pairs; cols: tx*8 + {0..7}
    unsigned long long acc[4][8];
#pragma unroll
    for (int p = 0; p < 4; p++)
#pragma unroll
        for (int j = 0; j < 8; j++) acc[p][j] = pack2(0.f, 0.f);

#pragma unroll 4
    for (int k = 0; k < 32; k++) {
        float4 a0 = *(const float4*)&sAT[k * 132 + ty * 8];
        float4 a1 = *(const float4*)&sAT[k * 132 + ty * 8 + 4];
        unsigned long long ap[4];
        ap[0] = pack2(a0.x, a0.y); ap[1] = pack2(a0.z, a0.w);
        ap[2] = pack2(a1.x, a1.y); ap[3] = pack2(a1.z, a1.w);
#pragma unroll
        for (int j = 0; j < 8; j++) {
            float bv = sB[(tx * 8 + j) * 33 + k];
            unsigned long long bp = pack2(bv, bv);
#pragma unroll
            for (int p = 0; p < 4; p++) acc[p][j] = fma2(ap[p], bp, acc[p][j]);
        }
    }

    float* ob = out + ((size_t)(g * NPG + i0)) * NPG + j0;
#pragma unroll
    for (int p = 0; p < 4; p++) {
        float r0[8], r1[8];
#pragma unroll
        for (int j = 0; j < 8; j++) {
            unpack2(acc[p][j], r0[j], r1[j]);
            r0[j] = sigm(r0[j]);
            r1[j] = sigm(r1[j]);
        }
        int row0 = ty * 8 + 2 * p;
        float4* o0 = (float4*)&ob[(size_t)row0 * NPG + tx * 8];
        float4* o1 = (float4*)&ob[(size_t)(row0 + 1) * NPG + tx * 8];
        o0[0] = make_float4(r0[0], r0[1], r0[2], r0[3]);
        o0[1] = make_float4(r0[4], r0[5], r0[6], r0[7]);
        o1[0] = make_float4(r1[0], r1[1], r1[2], r1[3]);
        o1[1] = make_float4(r1[4], r1[5], r1[6], r1[7]);
    }
}

// ---------------- launch ---------------------------------------------------
extern "C" void kernel_launch(void* const* d_in, const int* in_sizes, int n_in,
                              void* d_out, int out_size) {
    const float* features = (const float*)d_in[0];
    const int*   src      = (const int*)d_in[1];
    const int*   dst      = (const int*)d_in[2];
    const float* noise    = (const float*)d_in[3];
    const float* W1       = (const float*)d_in[4];
    const float* b1       = (const float*)d_in[5];
    const float* W2       = (const float*)d_in[6];
    const float* b2       = (const float*)d_in[7];
    const float* W3       = (const float*)d_in[8];
    const float* b3       = (const float*)d_in[9];

    float* out      = (float*)d_out;
    float* out_adj  = out;
    float* out_mean = out + MEAN_OFF;
    float* out_ls   = out + LS_OFF;

    k_zero<<<NN / 256, 256>>>();
    k_count<<<EE / 256, 256>>>(src, dst);
    k_rsqrt<<<NN / 256, 256>>>();
    k_scan1<<<64, 1024>>>();
    k_scan2<<<1, 32>>>();
    k_scan3<<<64, 1024>>>();
    k_csr<<<EE / 256, 256>>>(src, dst);
    k_layer1<<<NN / 8, 256>>>(features, W1, b1);
    k_p<<<NN / 8, 256>>>(W2, W3);
    k_agg2z<<<NN / 8, 256>>>(noise, b2, b3, out_mean, out_ls);
    k_adj<<<dim3(8, 8, BB), 256>>>(out_adj);
}

// round 2
// speedup vs baseline: 1.8638x; 1.8638x over previous
#include <cuda_runtime.h>
#include <math.h>

#define BB   64
#define NPG  1024
#define NN   (BB * NPG)       // 65536 nodes
#define EE   (BB * 16384)     // 1048576 edges
#define INF  64
#define HIDF 128
#define OUTF 32

#define ADJ_ELEMS  ((size_t)BB * NPG * NPG)   // 67108864
#define MEAN_OFF   ADJ_ELEMS
#define LS_OFF     (ADJ_ELEMS + (size_t)NN * OUTF)

// ---------------- scratch (static device globals; no runtime alloc) -------
__device__ int   g_cnt_out[NN];
__device__ int   g_cnt_in[NN];
__device__ float g_rs_out[NN];
__device__ float g_rs_in[NN];
__device__ int   g_rowptr[NN + 1];
__device__ int   g_bsum[64];
__device__ int   g_fill[NN];
__device__ int   g_csr[EE];
__device__ float g_a[NN * INF];    // aggregated+scaled input features
__device__ float g_h[NN * HIDF];   // layer-1 output (relu'd)
__device__ float g_p[NN * 64];     // (h * rs_out) @ [W2 | W3]
__device__ float g_z[NN * OUTF];   // latent z

typedef unsigned long long u64;

// ---------------- f32x2 helpers (FFMA2) -----------------------------------
__device__ __forceinline__ u64 pack2(float lo, float hi) {
    u64 r;
    asm("mov.b64 %0, {%1, %2};" : "=l"(r) : "f"(lo), "f"(hi));
    return r;
}
__device__ __forceinline__ u64 fma2(u64 a, u64 b, u64 c) {
    u64 d;
    asm("fma.rn.f32x2 %0, %1, %2, %3;" : "=l"(d) : "l"(a), "l"(b), "l"(c));
    return d;
}
__device__ __forceinline__ void unpack2(u64 v, float& a, float& b) {
    asm("mov.b64 {%0, %1}, %2;" : "=f"(a), "=f"(b) : "l"(v));
}
__device__ __forceinline__ float sigm(float x) {
    return __fdividef(1.0f, 1.0f + __expf(-x));   // MUFU.EX2 + MUFU.RCP
}

// ---------------- setup kernels -------------------------------------------
__global__ void k_zero() {
    int i = blockIdx.x * blockDim.x + threadIdx.x;
    if (i < NN) { g_cnt_out[i] = 0; g_cnt_in[i] = 0; g_fill[i] = 0; }
}

__global__ void k_count(const int* __restrict__ src, const int* __restrict__ dst) {
    int e = blockIdx.x * blockDim.x + threadIdx.x;
    if (e < EE) {
        atomicAdd(&g_cnt_out[src[e]], 1);
        atomicAdd(&g_cnt_in[dst[e]], 1);
    }
}

// exclusive scan of g_cnt_in -> g_rowptr; also rs_in
__global__ void k_scan1() {
    __shared__ int sh[1024];
    int t = threadIdx.x;
    int i = blockIdx.x * 1024 + t;
    int v = g_cnt_in[i];
    sh[t] = v;
    __syncthreads();
    for (int ofs = 1; ofs < 1024; ofs <<= 1) {
        int x = (t >= ofs) ? sh[t - ofs] : 0;
        __syncthreads();
        sh[t] += x;
        __syncthreads();
    }
    g_rowptr[i] = sh[t] - v;            // exclusive within block
    g_rs_in[i] = rsqrtf((float)max(v, 1));
    if (t == 1023) g_bsum[blockIdx.x] = sh[t];
}

// add block prefix (computed locally), rs_out, rowptr[NN]
__global__ void k_scan3() {
    __shared__ int s_pre;
    if (threadIdx.x == 0) {
        int s = 0;
        for (int j = 0; j < blockIdx.x; j++) s += g_bsum[j];
        s_pre = s;
    }
    __syncthreads();
    int i = blockIdx.x * 1024 + threadIdx.x;
    g_rowptr[i] += s_pre;
    g_rs_out[i] = rsqrtf((float)max(g_cnt_out[i], 1));
    if (i == NN - 1) g_rowptr[NN] = EE;
}

__global__ void k_csr(const int* __restrict__ src, const int* __restrict__ dst) {
    int e = blockIdx.x * blockDim.x + threadIdx.x;
    if (e < EE) {
        int d = dst[e];
        int pos = g_rowptr[d] + atomicAdd(&g_fill[d], 1);
        g_csr[pos] = src[e];
    }
}

// ---------------- layer-1 aggregation: warp per node ----------------------
__global__ __launch_bounds__(256) void k_agg1(const float* __restrict__ feat) {
    int tid = threadIdx.x;
    int warp = tid >> 5, lane = tid & 31;
    int n = blockIdx.x * 8 + warp;

    int beg = g_rowptr[n], end = g_rowptr[n + 1];
    float a0 = 0.f, a1 = 0.f;
    for (int e = beg; e < end; e++) {
        int s = g_csr[e];
        float rs = g_rs_out[s];
        const float* f = feat + s * INF;
        a0 = fmaf(f[lane], rs, a0);
        a1 = fmaf(f[lane + 32], rs, a1);
    }
    float rin = g_rs_in[n];
    g_a[n * INF + lane]      = a0 * rin;
    g_a[n * INF + lane + 32] = a1 * rin;
}

// ---------------- GEMM1: h = relu(a @ W1 + b1)  [65536x64]@[64x128] -------
// block: 128 nodes x 128 cols; 256 thr; thread 8x8; K chunks of 32
__global__ __launch_bounds__(256, 2) void k_gemm1(const float* __restrict__ W1,
                                                  const float* __restrict__ b1) {
    __shared__ __align__(16) float sA[32 * 132];
    __shared__ __align__(16) float sW[32 * 128];
    __shared__ float sb[128];
    int tid = threadIdx.x;
    int n0 = blockIdx.x * 128;
    if (tid < 128) sb[tid] = b1[tid];
    int tx = tid & 15, ty = tid >> 4;

    u64 acc[8][4];
#pragma unroll
    for (int r = 0; r < 8; r++)
#pragma unroll
        for (int cp = 0; cp < 4; cp++) acc[r][cp] = 0ull;

    for (int kc = 0; kc < 2; kc++) {
        __syncthreads();
#pragma unroll
        for (int it = 0; it < 4; it++) {
            int idx = it * 256 + tid;              // float4 idx, 1024 total
            int r = idx >> 3, k4 = (idx & 7) * 4;
            float4 v = *(const float4*)&g_a[(n0 + r) * INF + kc * 32 + k4];
            sA[(k4 + 0) * 132 + r] = v.x;
            sA[(k4 + 1) * 132 + r] = v.y;
            sA[(k4 + 2) * 132 + r] = v.z;
            sA[(k4 + 3) * 132 + r] = v.w;
        }
#pragma unroll
        for (int it = 0; it < 4; it++) {
            int idx = it * 256 + tid;
            ((float4*)sW)[idx] = ((const float4*)(W1 + kc * 32 * 128))[idx];
        }
        __syncthreads();
#pragma unroll 4
        for (int k = 0; k < 32; k++) {
            const float* Ak = &sA[k * 132];
            const float* Wk = &sW[k * 128];
            float4 a0 = *(const float4*)&Ak[ty * 8];
            float4 a1 = *(const float4*)&Ak[ty * 8 + 4];
            float4 w0 = *(const float4*)&Wk[tx * 8];
            float4 w1 = *(const float4*)&Wk[tx * 8 + 4];
            u64 bp[4] = {pack2(w0.x, w0.y), pack2(w0.z, w0.w),
                         pack2(w1.x, w1.y), pack2(w1.z, w1.w)};
            float ar[8] = {a0.x, a0.y, a0.z, a0.w, a1.x, a1.y, a1.z, a1.w};
#pragma unroll
            for (int r = 0; r < 8; r++) {
                u64 ab = pack2(ar[r], ar[r]);
#pragma unroll
                for (int cp = 0; cp < 4; cp++) acc[r][cp] = fma2(ab, bp[cp], acc[r][cp]);
            }
        }
    }
#pragma unroll
    for (int r = 0; r < 8; r++) {
        float v[8];
#pragma unroll
        for (int cp = 0; cp < 4; cp++) {
            float x, y;
            unpack2(acc[r][cp], x, y);
            v[2 * cp]     = fmaxf(x + sb[tx * 8 + 2 * cp], 0.f);
            v[2 * cp + 1] = fmaxf(y + sb[tx * 8 + 2 * cp + 1], 0.f);
        }
        float* o = &g_h[(n0 + ty * 8 + r) * HIDF + tx * 8];
        *(float4*)&o[0] = make_float4(v[0], v[1], v[2], v[3]);
        *(float4*)&o[4] = make_float4(v[4], v[5], v[6], v[7]);
    }
}

// ---------------- GEMM-P: p = (h*rs_out) @ [W2|W3]  [65536x128]@[128x64] --
// block: 128 nodes x 64 cols; 256 thr; thread 8x4; K chunks of 32
__global__ __launch_bounds__(256, 2) void k_gemm_p(const float* __restrict__ W2,
                                                   const float* __restrict__ W3) {
    __shared__ __align__(16) float sA[32 * 132];
    __shared__ __align__(16) float sW[32 * 64];
    int tid = threadIdx.x;
    int n0 = blockIdx.x * 128;
    int tx = tid & 15, ty = tid >> 4;

    u64 acc[8][2];
#pragma unroll
    for (int r = 0; r < 8; r++) { acc[r][0] = 0ull; acc[r][1] = 0ull; }

    for (int kc = 0; kc < 4; kc++) {
        __syncthreads();
#pragma unroll
        for (int it = 0; it < 4; it++) {
            int idx = it * 256 + tid;              // float4 idx, 1024 total
            int r = idx >> 3, k4 = (idx & 7) * 4;
            float rs = g_rs_out[n0 + r];
            float4 v = *(const float4*)&g_h[(n0 + r) * HIDF + kc * 32 + k4];
            sA[(k4 + 0) * 132 + r] = v.x * rs;
            sA[(k4 + 1) * 132 + r] = v.y * rs;
            sA[(k4 + 2) * 132 + r] = v.z * rs;
            sA[(k4 + 3) * 132 + r] = v.w * rs;
        }
        {
            // stage W rows kc*32..+31 into [k][64] combined [W2|W3]
            int idx = tid;                          // float4 idx, 512 total
            for (int it = 0; it < 2; it++, idx += 256) {
                int k = idx >> 4, c4 = (idx & 15) * 4;
                int kr = kc * 32 + k;
                float4 v;
                if (c4 < 32) v = *(const float4*)&W2[kr * 32 + c4];
                else         v = *(const float4*)&W3[kr * 32 + (c4 - 32)];
                *(float4*)&sW[k * 64 + c4] = v;
            }
        }
        __syncthreads();
#pragma unroll 4
        for (int k = 0; k < 32; k++) {
            const float* Ak = &sA[k * 132];
            const float* Wk = &sW[k * 64];
            float4 a0 = *(const float4*)&Ak[ty * 8];
            float4 a1 = *(const float4*)&Ak[ty * 8 + 4];
            float4 w0 = *(const float4*)&Wk[tx * 4];
            u64 bp[2] = {pack2(w0.x, w0.y), pack2(w0.z, w0.w)};
            float ar[8] = {a0.x, a0.y, a0.z, a0.w, a1.x, a1.y, a1.z, a1.w};
#pragma unroll
            for (int r = 0; r < 8; r++) {
                u64 ab = pack2(ar[r], ar[r]);
                acc[r][0] = fma2(ab, bp[0], acc[r][0]);
                acc[r][1] = fma2(ab, bp[1], acc[r][1]);
            }
        }
    }
#pragma unroll
    for (int r = 0; r < 8; r++) {
        float v[4];
        unpack2(acc[r][0], v[0], v[1]);
        unpack2(acc[r][1], v[2], v[3]);
        *(float4*)&g_p[(n0 + ty * 8 + r) * 64 + tx * 4] = make_float4(v[0], v[1], v[2], v[3]);
    }
}

// ---------------- aggregate p, add bias, z = mean + noise*exp(ls) ---------
__global__ __launch_bounds__(256) void k_agg2z(const float* __restrict__ noise,
                                               const float* __restrict__ b2,
                                               const float* __restrict__ b3,
                                               float* __restrict__ out_mean,
                                               float* __restrict__ out_ls) {
    int tid = threadIdx.x;
    int warp = tid >> 5, lane = tid & 31;
    int n = blockIdx.x * 8 + warp;

    int beg = g_rowptr[n], end = g_rowptr[n + 1];
    float a0 = 0.f, a1 = 0.f;
    for (int e = beg; e < end; e++) {
        int s = g_csr[e];
        const float* p = g_p + s * 64;
        a0 += p[lane];
        a1 += p[lane + 32];
    }
    float rin = g_rs_in[n];
    float mean = fmaf(a0, rin, b2[lane]);
    float ls   = fmaf(a1, rin, b3[lane]);
    float z    = fmaf(noise[n * OUTF + lane], __expf(ls), mean);
    out_mean[n * OUTF + lane] = mean;
    out_ls[n * OUTF + lane]   = ls;
    g_z[n * OUTF + lane]      = z;
}

// ---------------- adj = sigmoid(Z Z^T) per graph, 128x128 tiles -----------
// grid (8, 8, 64); block 256; thread 8x8; A and B both staged [k][idx]
__global__ __launch_bounds__(256, 2) void k_adj(float* __restrict__ out) {
    __shared__ __align__(16) float sA[32 * 132];
    __shared__ __align__(16) float sB[32 * 132];

    int g  = blockIdx.z;
    int i0 = blockIdx.y * 128, j0 = blockIdx.x * 128;
    const float4* zA4 = (const float4*)(g_z + ((size_t)(g * NPG + i0)) * OUTF);
    const float4* zB4 = (const float4*)(g_z + ((size_t)(g * NPG + j0)) * OUTF);
    int tid = threadIdx.x;

#pragma unroll
    for (int it = 0; it < 4; it++) {
        int idx = it * 256 + tid;                  // float4 idx, 1024 total
        int r = idx >> 3, k4 = (idx & 7) * 4;
        float4 va = zA4[idx];
        float4 vb = zB4[idx];
        sA[(k4 + 0) * 132 + r] = va.x;
        sA[(k4 + 1) * 132 + r] = va.y;
        sA[(k4 + 2) * 132 + r] = va.z;
        sA[(k4 + 3) * 132 + r] = va.w;
        sB[(k4 + 0) * 132 + r] = vb.x;
        sB[(k4 + 1) * 132 + r] = vb.y;
        sB[(k4 + 2) * 132 + r] = vb.z;
        sB[(k4 + 3) * 132 + r] = vb.w;
    }
    __syncthreads();

    int tx = tid & 15, ty = tid >> 4;
    u64 acc[8][4];
#pragma unroll
    for (int r = 0; r < 8; r++)
#pragma unroll
        for (int cp = 0; cp < 4; cp++) acc[r][cp] = 0ull;

#pragma unroll 4
    for (int k = 0; k < 32; k++) {
        const float* Ak = &sA[k * 132];
        const float* Bk = &sB[k * 132];
        float4 a0 = *(const float4*)&Ak[ty * 8];
        float4 a1 = *(const float4*)&Ak[ty * 8 + 4];
        float4 b0 = *(const float4*)&Bk[tx * 8];
        float4 b1 = *(const float4*)&Bk[tx * 8 + 4];
        u64 bp[4] = {pack2(b0.x, b0.y), pack2(b0.z, b0.w),
                     pack2(b1.x, b1.y), pack2(b1.z, b1.w)};
        float ar[8] = {a0.x, a0.y, a0.z, a0.w, a1.x, a1.y, a1.z, a1.w};
#pragma unroll
        for (int r = 0; r < 8; r++) {
            u64 ab = pack2(ar[r], ar[r]);
#pragma unroll
            for (int cp = 0; cp < 4; cp++) acc[r][cp] = fma2(ab, bp[cp], acc[r][cp]);
        }
    }

    float* ob = out + ((size_t)(g * NPG + i0)) * NPG + j0;
#pragma unroll
    for (int r = 0; r < 8; r++) {
        float v[8];
#pragma unroll
        for (int cp = 0; cp < 4; cp++) {
            float x, y;
            unpack2(acc[r][cp], x, y);
            v[2 * cp]     = sigm(x);
            v[2 * cp + 1] = sigm(y);
        }
        float* o = &ob[(size_t)(ty * 8 + r) * NPG + tx * 8];
        *(float4*)&o[0] = make_float4(v[0], v[1], v[2], v[3]);
        *(float4*)&o[4] = make_float4(v[4], v[5], v[6], v[7]);
    }
}

// ---------------- launch ---------------------------------------------------
extern "C" void kernel_launch(void* const* d_in, const int* in_sizes, int n_in,
                              void* d_out, int out_size) {
    const float* features = (const float*)d_in[0];
    const int*   src      = (const int*)d_in[1];
    const int*   dst      = (const int*)d_in[2];
    const float* noise    = (const float*)d_in[3];
    const float* W1       = (const float*)d_in[4];
    const float* b1       = (const float*)d_in[5];
    const float* W2       = (const float*)d_in[6];
    const float* b2       = (const float*)d_in[7];
    const float* W3       = (const float*)d_in[8];
    const float* b3       = (const float*)d_in[9];

    float* out      = (float*)d_out;
    float* out_adj  = out;
    float* out_mean = out + MEAN_OFF;
    float* out_ls   = out + LS_OFF;

    k_zero<<<NN / 256, 256>>>();
    k_count<<<EE / 256, 256>>>(src, dst);
    k_scan1<<<64, 1024>>>();
    k_scan3<<<64, 1024>>>();
    k_csr<<<EE / 256, 256>>>(src, dst);
    k_agg1<<<NN / 8, 256>>>(features);
    k_gemm1<<<512, 256>>>(W1, b1);
    k_gemm_p<<<512, 256>>>(W2, W3);
    k_agg2z<<<NN / 8, 256>>>(noise, b2, b3, out_mean, out_ls);
    k_adj<<<dim3(8, 8, BB), 256>>>(out_adj);
}

// round 3
// speedup vs baseline: 1.9738x; 1.0590x over previous
#include <cuda_runtime.h>
#include <math.h>

#define BB   64
#define NPG  1024
#define NN   (BB * NPG)       // 65536 nodes
#define EE   (BB * 16384)     // 1048576 edges
#define INF  64
#define HIDF 128
#define OUTF 32

#define ADJ_ELEMS  ((size_t)BB * NPG * NPG)   // 67108864
#define MEAN_OFF   ADJ_ELEMS
#define LS_OFF     (ADJ_ELEMS + (size_t)NN * OUTF)

// ---------------- scratch (static device globals; no runtime alloc) -------
__device__ int   g_cnt_out[NN];
__device__ int   g_cnt_in[NN];
__device__ float g_rs_out[NN];
__device__ float g_rs_in[NN];
__device__ int   g_rowptr[NN + 1];
__device__ int   g_bsum[64];
__device__ int   g_fill[NN];
__device__ int   g_csr[EE];
__device__ float g_a[NN * INF];    // aggregated+scaled input features
__device__ float g_h[NN * HIDF];   // layer-1 output (relu'd)
__device__ float g_p[NN * 64];     // (h * rs_out) @ [W2 | W3]
__device__ float g_z[NN * OUTF];   // latent z

typedef unsigned long long u64;

// ---------------- f32x2 helpers (FFMA2) -----------------------------------
__device__ __forceinline__ u64 pack2(float lo, float hi) {
    u64 r;
    asm("mov.b64 %0, {%1, %2};" : "=l"(r) : "f"(lo), "f"(hi));
    return r;
}
__device__ __forceinline__ u64 fma2(u64 a, u64 b, u64 c) {
    u64 d;
    asm("fma.rn.f32x2 %0, %1, %2, %3;" : "=l"(d) : "l"(a), "l"(b), "l"(c));
    return d;
}
__device__ __forceinline__ void unpack2(u64 v, float& a, float& b) {
    asm("mov.b64 {%0, %1}, %2;" : "=f"(a), "=f"(b) : "l"(v));
}
__device__ __forceinline__ float sigm(float x) {
    return __fdividef(1.0f, 1.0f + __expf(-x));   // MUFU.EX2 + MUFU.RCP
}

// ---------------- setup kernels -------------------------------------------
__global__ void k_zero() {
    int i = blockIdx.x * blockDim.x + threadIdx.x;
    if (i < NN) { g_cnt_out[i] = 0; g_cnt_in[i] = 0; g_fill[i] = 0; }
}

__global__ void k_count(const int* __restrict__ src, const int* __restrict__ dst) {
    int e = blockIdx.x * blockDim.x + threadIdx.x;
    if (e < EE) {
        atomicAdd(&g_cnt_out[src[e]], 1);
        atomicAdd(&g_cnt_in[dst[e]], 1);
    }
}

// exclusive scan of g_cnt_in -> g_rowptr; also rs_in
__global__ void k_scan1() {
    __shared__ int sh[1024];
    int t = threadIdx.x;
    int i = blockIdx.x * 1024 + t;
    int v = g_cnt_in[i];
    sh[t] = v;
    __syncthreads();
    for (int ofs = 1; ofs < 1024; ofs <<= 1) {
        int x = (t >= ofs) ? sh[t - ofs] : 0;
        __syncthreads();
        sh[t] += x;
        __syncthreads();
    }
    g_rowptr[i] = sh[t] - v;            // exclusive within block
    g_rs_in[i] = rsqrtf((float)max(v, 1));
    if (t == 1023) g_bsum[blockIdx.x] = sh[t];
}

// add block prefix, rs_out, rowptr[NN]; bsum staged via smem (parallel loads)
__global__ void k_scan3() {
    __shared__ int sbs[64];
    __shared__ int s_pre;
    if (threadIdx.x < 64) sbs[threadIdx.x] = g_bsum[threadIdx.x];
    __syncthreads();
    if (threadIdx.x == 0) {
        int s = 0, b = blockIdx.x;
        for (int j = 0; j < b; j++) s += sbs[j];
        s_pre = s;
    }
    __syncthreads();
    int i = blockIdx.x * 1024 + threadIdx.x;
    g_rowptr[i] += s_pre;
    g_rs_out[i] = rsqrtf((float)max(g_cnt_out[i], 1));
    if (i == NN - 1) g_rowptr[NN] = EE;
}

__global__ void k_csr(const int* __restrict__ src, const int* __restrict__ dst) {
    int e = blockIdx.x * blockDim.x + threadIdx.x;
    if (e < EE) {
        int d = dst[e];
        int pos = g_rowptr[d] + atomicAdd(&g_fill[d], 1);
        g_csr[pos] = src[e];
    }
}

// ---------------- layer-1 aggregation: warp per node, 4-wide unroll -------
__global__ __launch_bounds__(256) void k_agg1(const float* __restrict__ feat) {
    int tid = threadIdx.x;
    int warp = tid >> 5, lane = tid & 31;
    int n = blockIdx.x * 8 + warp;

    int beg = g_rowptr[n], end = g_rowptr[n + 1];
    float a0 = 0.f, a1 = 0.f;
    int e = beg;
    for (; e + 3 < end; e += 4) {
        int s0 = g_csr[e], s1 = g_csr[e + 1], s2 = g_csr[e + 2], s3 = g_csr[e + 3];
        float r0 = g_rs_out[s0], r1 = g_rs_out[s1];
        float r2 = g_rs_out[s2], r3 = g_rs_out[s3];
        const float* f0 = feat + s0 * INF;
        const float* f1 = feat + s1 * INF;
        const float* f2 = feat + s2 * INF;
        const float* f3 = feat + s3 * INF;
        float x0 = f0[lane], x1 = f1[lane], x2 = f2[lane], x3 = f3[lane];
        float y0 = f0[lane + 32], y1 = f1[lane + 32];
        float y2 = f2[lane + 32], y3 = f3[lane + 32];
        a0 = fmaf(x0, r0, fmaf(x1, r1, fmaf(x2, r2, fmaf(x3, r3, a0))));
        a1 = fmaf(y0, r0, fmaf(y1, r1, fmaf(y2, r2, fmaf(y3, r3, a1))));
    }
    for (; e < end; e++) {
        int s = g_csr[e];
        float rs = g_rs_out[s];
        const float* f = feat + s * INF;
        a0 = fmaf(f[lane], rs, a0);
        a1 = fmaf(f[lane + 32], rs, a1);
    }
    float rin = g_rs_in[n];
    g_a[n * INF + lane]      = a0 * rin;
    g_a[n * INF + lane + 32] = a1 * rin;
}

// ---------------- GEMM1: h = relu(a @ W1 + b1)  [65536x64]@[64x128] -------
__global__ __launch_bounds__(256, 2) void k_gemm1(const float* __restrict__ W1,
                                                  const float* __restrict__ b1) {
    __shared__ __align__(16) float sA[32 * 132];
    __shared__ __align__(16) float sW[32 * 128];
    __shared__ float sb[128];
    int tid = threadIdx.x;
    int n0 = blockIdx.x * 128;
    if (tid < 128) sb[tid] = b1[tid];
    int tx = tid & 15, ty = tid >> 4;

    u64 acc[8][4];
#pragma unroll
    for (int r = 0; r < 8; r++)
#pragma unroll
        for (int cp = 0; cp < 4; cp++) acc[r][cp] = 0ull;

    for (int kc = 0; kc < 2; kc++) {
        __syncthreads();
#pragma unroll
        for (int it = 0; it < 4; it++) {
            int idx = it * 256 + tid;              // float4 idx, 1024 total
            int r = idx >> 3, k4 = (idx & 7) * 4;
            float4 v = *(const float4*)&g_a[(n0 + r) * INF + kc * 32 + k4];
            sA[(k4 + 0) * 132 + r] = v.x;
            sA[(k4 + 1) * 132 + r] = v.y;
            sA[(k4 + 2) * 132 + r] = v.z;
            sA[(k4 + 3) * 132 + r] = v.w;
        }
#pragma unroll
        for (int it = 0; it < 4; it++) {
            int idx = it * 256 + tid;
            ((float4*)sW)[idx] = ((const float4*)(W1 + kc * 32 * 128))[idx];
        }
        __syncthreads();
#pragma unroll 4
        for (int k = 0; k < 32; k++) {
            const float* Ak = &sA[k * 132];
            const float* Wk = &sW[k * 128];
            float4 a0 = *(const float4*)&Ak[ty * 8];
            float4 a1 = *(const float4*)&Ak[ty * 8 + 4];
            float4 w0 = *(const float4*)&Wk[tx * 8];
            float4 w1 = *(const float4*)&Wk[tx * 8 + 4];
            u64 bp[4] = {pack2(w0.x, w0.y), pack2(w0.z, w0.w),
                         pack2(w1.x, w1.y), pack2(w1.z, w1.w)};
            float ar[8] = {a0.x, a0.y, a0.z, a0.w, a1.x, a1.y, a1.z, a1.w};
#pragma unroll
            for (int r = 0; r < 8; r++) {
                u64 ab = pack2(ar[r], ar[r]);
#pragma unroll
                for (int cp = 0; cp < 4; cp++) acc[r][cp] = fma2(ab, bp[cp], acc[r][cp]);
            }
        }
    }
#pragma unroll
    for (int r = 0; r < 8; r++) {
        float v[8];
#pragma unroll
        for (int cp = 0; cp < 4; cp++) {
            float x, y;
            unpack2(acc[r][cp], x, y);
            v[2 * cp]     = fmaxf(x + sb[tx * 8 + 2 * cp], 0.f);
            v[2 * cp + 1] = fmaxf(y + sb[tx * 8 + 2 * cp + 1], 0.f);
        }
        float* o = &g_h[(n0 + ty * 8 + r) * HIDF + tx * 8];
        *(float4*)&o[0] = make_float4(v[0], v[1], v[2], v[3]);
        *(float4*)&o[4] = make_float4(v[4], v[5], v[6], v[7]);
    }
}

// ---------------- GEMM-P: p = (h*rs_out) @ [W2|W3]  [65536x128]@[128x64] --
__global__ __launch_bounds__(256, 2) void k_gemm_p(const float* __restrict__ W2,
                                                   const float* __restrict__ W3) {
    __shared__ __align__(16) float sA[32 * 132];
    __shared__ __align__(16) float sW[32 * 64];
    int tid = threadIdx.x;
    int n0 = blockIdx.x * 128;
    int tx = tid & 15, ty = tid >> 4;

    u64 acc[8][2];
#pragma unroll
    for (int r = 0; r < 8; r++) { acc[r][0] = 0ull; acc[r][1] = 0ull; }

    for (int kc = 0; kc < 4; kc++) {
        __syncthreads();
#pragma unroll
        for (int it = 0; it < 4; it++) {
            int idx = it * 256 + tid;              // float4 idx, 1024 total
            int r = idx >> 3, k4 = (idx & 7) * 4;
            float rs = g_rs_out[n0 + r];
            float4 v = *(const float4*)&g_h[(n0 + r) * HIDF + kc * 32 + k4];
            sA[(k4 + 0) * 132 + r] = v.x * rs;
            sA[(k4 + 1) * 132 + r] = v.y * rs;
            sA[(k4 + 2) * 132 + r] = v.z * rs;
            sA[(k4 + 3) * 132 + r] = v.w * rs;
        }
        {
            int idx = tid;                          // float4 idx, 512 total
            for (int it = 0; it < 2; it++, idx += 256) {
                int k = idx >> 4, c4 = (idx & 15) * 4;
                int kr = kc * 32 + k;
                float4 v;
                if (c4 < 32) v = *(const float4*)&W2[kr * 32 + c4];
                else         v = *(const float4*)&W3[kr * 32 + (c4 - 32)];
                *(float4*)&sW[k * 64 + c4] = v;
            }
        }
        __syncthreads();
#pragma unroll 4
        for (int k = 0; k < 32; k++) {
            const float* Ak = &sA[k * 132];
            const float* Wk = &sW[k * 64];
            float4 a0 = *(const float4*)&Ak[ty * 8];
            float4 a1 = *(const float4*)&Ak[ty * 8 + 4];
            float4 w0 = *(const float4*)&Wk[tx * 4];
            u64 bp[2] = {pack2(w0.x, w0.y), pack2(w0.z, w0.w)};
            float ar[8] = {a0.x, a0.y, a0.z, a0.w, a1.x, a1.y, a1.z, a1.w};
#pragma unroll
            for (int r = 0; r < 8; r++) {
                u64 ab = pack2(ar[r], ar[r]);
                acc[r][0] = fma2(ab, bp[0], acc[r][0]);
                acc[r][1] = fma2(ab, bp[1], acc[r][1]);
            }
        }
    }
#pragma unroll
    for (int r = 0; r < 8; r++) {
        float v[4];
        unpack2(acc[r][0], v[0], v[1]);
        unpack2(acc[r][1], v[2], v[3]);
        *(float4*)&g_p[(n0 + ty * 8 + r) * 64 + tx * 4] = make_float4(v[0], v[1], v[2], v[3]);
    }
}

// ---------------- aggregate p, add bias, z = mean + noise*exp(ls) ---------
__global__ __launch_bounds__(256) void k_agg2z(const float* __restrict__ noise,
                                               const float* __restrict__ b2,
                                               const float* __restrict__ b3,
                                               float* __restrict__ out_mean,
                                               float* __restrict__ out_ls) {
    int tid = threadIdx.x;
    int warp = tid >> 5, lane = tid & 31;
    int n = blockIdx.x * 8 + warp;

    int beg = g_rowptr[n], end = g_rowptr[n + 1];
    float a0 = 0.f, a1 = 0.f;
    int e = beg;
    for (; e + 3 < end; e += 4) {
        int s0 = g_csr[e], s1 = g_csr[e + 1], s2 = g_csr[e + 2], s3 = g_csr[e + 3];
        const float* p0 = g_p + s0 * 64;
        const float* p1 = g_p + s1 * 64;
        const float* p2 = g_p + s2 * 64;
        const float* p3 = g_p + s3 * 64;
        float x0 = p0[lane], x1 = p1[lane], x2 = p2[lane], x3 = p3[lane];
        float y0 = p0[lane + 32], y1 = p1[lane + 32];
        float y2 = p2[lane + 32], y3 = p3[lane + 32];
        a0 += (x0 + x1) + (x2 + x3);
        a1 += (y0 + y1) + (y2 + y3);
    }
    for (; e < end; e++) {
        int s = g_csr[e];
        const float* p = g_p + s * 64;
        a0 += p[lane];
        a1 += p[lane + 32];
    }
    float rin = g_rs_in[n];
    float mean = fmaf(a0, rin, b2[lane]);
    float ls   = fmaf(a1, rin, b3[lane]);
    float z    = fmaf(noise[n * OUTF + lane], __expf(ls), mean);
    out_mean[n * OUTF + lane] = mean;
    out_ls[n * OUTF + lane]   = ls;
    g_z[n * OUTF + lane]      = z;
}

// ---------------- adj = sigmoid(Z Z^T): upper-tri tiles + mirrored write --
// grid (36, 64); block 256; thread 8x8; A and B staged [k][idx] padded 132
__global__ __launch_bounds__(256, 2) void k_adj(float* __restrict__ out) {
    __shared__ __align__(16) float sA[32 * 132];
    __shared__ __align__(16) float sB[32 * 132];

    int g = blockIdx.y;
    // map linear tile id -> (bi, bj) with bi <= bj over an 8x8 tile grid
    int t = blockIdx.x, bi = 0;
    while (t >= 8 - bi) { t -= 8 - bi; bi++; }
    int bj = bi + t;
    int i0 = bi * 128, j0 = bj * 128;

    const float4* zA4 = (const float4*)(g_z + ((size_t)(g * NPG + i0)) * OUTF);
    const float4* zB4 = (const float4*)(g_z + ((size_t)(g * NPG + j0)) * OUTF);
    int tid = threadIdx.x;

#pragma unroll
    for (int it = 0; it < 4; it++) {
        int idx = it * 256 + tid;                  // float4 idx, 1024 total
        int r = idx >> 3, k4 = (idx & 7) * 4;
        float4 va = zA4[idx];
        float4 vb = zB4[idx];
        sA[(k4 + 0) * 132 + r] = va.x;
        sA[(k4 + 1) * 132 + r] = va.y;
        sA[(k4 + 2) * 132 + r] = va.z;
        sA[(k4 + 3) * 132 + r] = va.w;
        sB[(k4 + 0) * 132 + r] = vb.x;
        sB[(k4 + 1) * 132 + r] = vb.y;
        sB[(k4 + 2) * 132 + r] = vb.z;
        sB[(k4 + 3) * 132 + r] = vb.w;
    }
    __syncthreads();

    int tx = tid & 15, ty = tid >> 4;
    u64 acc[8][4];
#pragma unroll
    for (int r = 0; r < 8; r++)
#pragma unroll
        for (int cp = 0; cp < 4; cp++) acc[r][cp] = 0ull;

#pragma unroll 4
    for (int k = 0; k < 32; k++) {
        const float* Ak = &sA[k * 132];
        const float* Bk = &sB[k * 132];
        float4 a0 = *(const float4*)&Ak[ty * 8];
        float4 a1 = *(const float4*)&Ak[ty * 8 + 4];
        float4 b0 = *(const float4*)&Bk[tx * 8];
        float4 b1 = *(const float4*)&Bk[tx * 8 + 4];
        u64 bp[4] = {pack2(b0.x, b0.y), pack2(b0.z, b0.w),
                     pack2(b1.x, b1.y), pack2(b1.z, b1.w)};
        float ar[8] = {a0.x, a0.y, a0.z, a0.w, a1.x, a1.y, a1.z, a1.w};
#pragma unroll
        for (int r = 0; r < 8; r++) {
            u64 ab = pack2(ar[r], ar[r]);
#pragma unroll
            for (int cp = 0; cp < 4; cp++) acc[r][cp] = fma2(ab, bp[cp], acc[r][cp]);
        }
    }

    // sigmoids into 8x8 register block
    float m[8][8];
#pragma unroll
    for (int r = 0; r < 8; r++)
#pragma unroll
        for (int cp = 0; cp < 4; cp++) {
            float x, y;
            unpack2(acc[r][cp], x, y);
            m[r][2 * cp]     = sigm(x);
            m[r][2 * cp + 1] = sigm(y);
        }

    // normal tile (i0, j0)
    float* ob = out + ((size_t)(g * NPG + i0)) * NPG + j0;
#pragma unroll
    for (int r = 0; r < 8; r++) {
        float* o = &ob[(size_t)(ty * 8 + r) * NPG + tx * 8];
        *(float4*)&o[0] = make_float4(m[r][0], m[r][1], m[r][2], m[r][3]);
        *(float4*)&o[4] = make_float4(m[r][4], m[r][5], m[r][6], m[r][7]);
    }
    // mirror tile (j0, i0) — transpose from registers
    if (bi != bj) {
        float* obT = out + ((size_t)(g * NPG + j0)) * NPG + i0;
#pragma unroll
        for (int c = 0; c < 8; c++) {
            float* o = &obT[(size_t)(tx * 8 + c) * NPG + ty * 8];
            *(float4*)&o[0] = make_float4(m[0][c], m[1][c], m[2][c], m[3][c]);
            *(float4*)&o[4] = make_float4(m[4][c], m[5][c], m[6][c], m[7][c]);
        }
    }
}

// ---------------- launch ---------------------------------------------------
extern "C" void kernel_launch(void* const* d_in, const int* in_sizes, int n_in,
                              void* d_out, int out_size) {
    const float* features = (const float*)d_in[0];
    const int*   src      = (const int*)d_in[1];
    const int*   dst      = (const int*)d_in[2];
    const float* noise    = (const float*)d_in[3];
    const float* W1       = (const float*)d_in[4];
    const float* b1       = (const float*)d_in[5];
    const float* W2       = (const float*)d_in[6];
    const float* b2       = (const float*)d_in[7];
    const float* W3       = (const float*)d_in[8];
    const float* b3       = (const float*)d_in[9];

    float* out      = (float*)d_out;
    float* out_adj  = out;
    float* out_mean = out + MEAN_OFF;
    float* out_ls   = out + LS_OFF;

    k_zero<<<NN / 256, 256>>>();
    k_count<<<EE / 256, 256>>>(src, dst);
    k_scan1<<<64, 1024>>>();
    k_scan3<<<64, 1024>>>();
    k_csr<<<EE / 256, 256>>>(src, dst);
    k_agg1<<<NN / 8, 256>>>(features);
    k_gemm1<<<512, 256>>>(W1, b1);
    k_gemm_p<<<512, 256>>>(W2, W3);
    k_agg2z<<<NN / 8, 256>>>(noise, b2, b3, out_mean, out_ls);
    k_adj<<<dim3(36, BB), 256>>>(out_adj);
}

// round 4
// speedup vs baseline: 2.0435x; 1.0353x over previous
#include <cuda_runtime.h>
#include <math.h>

#define BB   64
#define NPG  1024
#define NN   (BB * NPG)       // 65536 nodes
#define EE   (BB * 16384)     // 1048576 edges
#define EPG  16384            // edges per graph
#define INF  64
#define HIDF 128
#define OUTF 32

#define ADJ_ELEMS  ((size_t)BB * NPG * NPG)   // 67108864
#define MEAN_OFF   ADJ_ELEMS
#define LS_OFF     (ADJ_ELEMS + (size_t)NN * OUTF)

#define AGG_SMEM   (NPG * 32 * 4 + EPG * 4)   // 131072 + 65536 = 196608 B

// ---------------- scratch (static device globals; no runtime alloc) -------
__device__ float g_rs_out[NN];
__device__ float g_rs_in[NN];
__device__ int   g_rowptr[NN + 1];
__device__ int   g_csr[EE];
__device__ float g_a[NN * INF];    // aggregated+scaled input features
__device__ float g_h[NN * HIDF];   // layer-1 output (relu'd)
__device__ float g_p[NN * 64];     // (h * rs_out) @ [W2 | W3]
__device__ float g_q[NN * 64];     // aggregated p (pre-bias mean|log_std)
__device__ float g_z[NN * OUTF];   // latent z

typedef unsigned long long u64;

// ---------------- f32x2 helpers (FFMA2) -----------------------------------
__device__ __forceinline__ u64 pack2(float lo, float hi) {
    u64 r;
    asm("mov.b64 %0, {%1, %2};" : "=l"(r) : "f"(lo), "f"(hi));
    return r;
}
__device__ __forceinline__ u64 fma2(u64 a, u64 b, u64 c) {
    u64 d;
    asm("fma.rn.f32x2 %0, %1, %2, %3;" : "=l"(d) : "l"(a), "l"(b), "l"(c));
    return d;
}
__device__ __forceinline__ void unpack2(u64 v, float& a, float& b) {
    asm("mov.b64 {%0, %1}, %2;" : "=f"(a), "=f"(b) : "l"(v));
}
__device__ __forceinline__ float sigm(float x) {
    return __fdividef(1.0f, 1.0f + __expf(-x));   // MUFU.EX2 + MUFU.RCP
}

// ---------------- k_build: per-graph CSR (count+scan+scatter fused) -------
__global__ __launch_bounds__(1024) void k_build(const int* __restrict__ src,
                                                const int* __restrict__ dst) {
    __shared__ int s_cin[NPG];
    __shared__ int s_cout[NPG];
    __shared__ int s_scan[NPG];
    __shared__ int s_fill[NPG];
    int g = blockIdx.x, t = threadIdx.x;
    int base_n = g * NPG, base_e = g * EPG;

    s_cin[t] = 0; s_cout[t] = 0;
    __syncthreads();
#pragma unroll
    for (int it = 0; it < 16; it++) {
        int e = base_e + it * 1024 + t;
        atomicAdd(&s_cin[dst[e] - base_n], 1);
        atomicAdd(&s_cout[src[e] - base_n], 1);
    }
    __syncthreads();
    int v = s_cin[t];
    s_scan[t] = v;
    __syncthreads();
    for (int ofs = 1; ofs < 1024; ofs <<= 1) {
        int x = (t >= ofs) ? s_scan[t - ofs] : 0;
        __syncthreads();
        s_scan[t] += x;
        __syncthreads();
    }
    int excl = s_scan[t] - v;
    g_rowptr[base_n + t] = base_e + excl;
    g_rs_in[base_n + t]  = rsqrtf((float)max(v, 1));
    g_rs_out[base_n + t] = rsqrtf((float)max(s_cout[t], 1));
    s_fill[t] = excl;
    if (g == BB - 1 && t == 1023) g_rowptr[NN] = EE;
    __syncthreads();
#pragma unroll
    for (int it = 0; it < 16; it++) {
        int e = base_e + it * 1024 + t;
        int d = dst[e] - base_n;
        int pos = atomicAdd(&s_fill[d], 1);
        g_csr[base_e + pos] = src[e];
    }
}

// ---------------- smem-staged aggregation of input features ---------------
// grid (64 graphs, 2 halves); block 1024; stages 1024x32 scaled feats + csr
__global__ __launch_bounds__(1024) void k_agg1s(const float* __restrict__ feat) {
    extern __shared__ __align__(16) char s_raw[];
    float* s_f = (float*)s_raw;                    // 1024*32 floats
    int* s_csr = (int*)(s_raw + NPG * 32 * 4);     // 16384 ints
    int g = blockIdx.x, h = blockIdx.y;
    int base_n = g * NPG, base_e = g * EPG;
    int t = threadIdx.x;

#pragma unroll
    for (int it = 0; it < 8; it++) {
        int idx = it * 1024 + t;                   // 8192 float4s
        int row = idx >> 3, q = idx & 7;
        float rs = g_rs_out[base_n + row];
        float4 v = *(const float4*)&feat[(size_t)(base_n + row) * INF + h * 32 + q * 4];
        v.x *= rs; v.y *= rs; v.z *= rs; v.w *= rs;
        *(float4*)&s_f[row * 32 + q * 4] = v;
    }
#pragma unroll
    for (int it = 0; it < 4; it++) {
        ((int4*)s_csr)[it * 1024 + t] = ((const int4*)(g_csr + base_e))[it * 1024 + t];
    }
    __syncthreads();

    int warp = t >> 5, lane = t & 31;
#pragma unroll 1
    for (int i = 0; i < 32; i++) {
        int n = base_n + warp * 32 + i;
        int beg = g_rowptr[n] - base_e, end = g_rowptr[n + 1] - base_e;
        float a = 0.f;
        int e = beg;
        for (; e + 3 < end; e += 4) {
            int s0 = s_csr[e] - base_n,     s1 = s_csr[e + 1] - base_n;
            int s2 = s_csr[e + 2] - base_n, s3 = s_csr[e + 3] - base_n;
            a += (s_f[s0 * 32 + lane] + s_f[s1 * 32 + lane]) +
                 (s_f[s2 * 32 + lane] + s_f[s3 * 32 + lane]);
        }
        for (; e < end; e++) a += s_f[(s_csr[e] - base_n) * 32 + lane];
        g_a[(size_t)n * INF + h * 32 + lane] = a * g_rs_in[n];
    }
}

// ---------------- smem-staged aggregation of p -> q -----------------------
__global__ __launch_bounds__(1024) void k_agg2s() {
    extern __shared__ __align__(16) char s_raw[];
    float* s_f = (float*)s_raw;
    int* s_csr = (int*)(s_raw + NPG * 32 * 4);
    int g = blockIdx.x, h = blockIdx.y;
    int base_n = g * NPG, base_e = g * EPG;
    int t = threadIdx.x;

#pragma unroll
    for (int it = 0; it < 8; it++) {
        int idx = it * 1024 + t;
        int row = idx >> 3, q = idx & 7;
        float4 v = *(const float4*)&g_p[(size_t)(base_n + row) * 64 + h * 32 + q * 4];
        *(float4*)&s_f[row * 32 + q * 4] = v;
    }
#pragma unroll
    for (int it = 0; it < 4; it++) {
        ((int4*)s_csr)[it * 1024 + t] = ((const int4*)(g_csr + base_e))[it * 1024 + t];
    }
    __syncthreads();

    int warp = t >> 5, lane = t & 31;
#pragma unroll 1
    for (int i = 0; i < 32; i++) {
        int n = base_n + warp * 32 + i;
        int beg = g_rowptr[n] - base_e, end = g_rowptr[n + 1] - base_e;
        float a = 0.f;
        int e = beg;
        for (; e + 3 < end; e += 4) {
            int s0 = s_csr[e] - base_n,     s1 = s_csr[e + 1] - base_n;
            int s2 = s_csr[e + 2] - base_n, s3 = s_csr[e + 3] - base_n;
            a += (s_f[s0 * 32 + lane] + s_f[s1 * 32 + lane]) +
                 (s_f[s2 * 32 + lane] + s_f[s3 * 32 + lane]);
        }
        for (; e < end; e++) a += s_f[(s_csr[e] - base_n) * 32 + lane];
        g_q[(size_t)n * 64 + h * 32 + lane] = a * g_rs_in[n];
    }
}

// ---------------- z epilogue: mean/ls/z from q ----------------------------
__global__ __launch_bounds__(256) void k_z(const float* __restrict__ noise,
                                           const float* __restrict__ b2,
                                           const float* __restrict__ b3,
                                           float* __restrict__ out_mean,
                                           float* __restrict__ out_ls) {
    int idx = blockIdx.x * 256 + threadIdx.x;     // 0 .. NN*32-1
    int n = idx >> 5, l = idx & 31;
    float mean = g_q[(size_t)n * 64 + l] + b2[l];
    float ls   = g_q[(size_t)n * 64 + 32 + l] + b3[l];
    float z    = fmaf(noise[idx], __expf(ls), mean);
    out_mean[idx] = mean;
    out_ls[idx]   = ls;
    g_z[idx]      = z;
}

// ---------------- GEMM1: h = relu(a @ W1 + b1)  [65536x64]@[64x128] -------
__global__ __launch_bounds__(256, 2) void k_gemm1(const float* __restrict__ W1,
                                                  const float* __restrict__ b1) {
    __shared__ __align__(16) float sA[32 * 132];
    __shared__ __align__(16) float sW[32 * 128];
    __shared__ float sb[128];
    int tid = threadIdx.x;
    int n0 = blockIdx.x * 128;
    if (tid < 128) sb[tid] = b1[tid];
    int tx = tid & 15, ty = tid >> 4;

    u64 acc[8][4];
#pragma unroll
    for (int r = 0; r < 8; r++)
#pragma unroll
        for (int cp = 0; cp < 4; cp++) acc[r][cp] = 0ull;

    for (int kc = 0; kc < 2; kc++) {
        __syncthreads();
#pragma unroll
        for (int it = 0; it < 4; it++) {
            int idx = it * 256 + tid;              // float4 idx, 1024 total
            int r = idx >> 3, k4 = (idx & 7) * 4;
            float4 v = *(const float4*)&g_a[(size_t)(n0 + r) * INF + kc * 32 + k4];
            sA[(k4 + 0) * 132 + r] = v.x;
            sA[(k4 + 1) * 132 + r] = v.y;
            sA[(k4 + 2) * 132 + r] = v.z;
            sA[(k4 + 3) * 132 + r] = v.w;
        }
#pragma unroll
        for (int it = 0; it < 4; it++) {
            int idx = it * 256 + tid;
            ((float4*)sW)[idx] = ((const float4*)(W1 + kc * 32 * 128))[idx];
        }
        __syncthreads();
#pragma unroll 4
        for (int k = 0; k < 32; k++) {
            const float* Ak = &sA[k * 132];
            const float* Wk = &sW[k * 128];
            float4 a0 = *(const float4*)&Ak[ty * 8];
            float4 a1 = *(const float4*)&Ak[ty * 8 + 4];
            float4 w0 = *(const float4*)&Wk[tx * 8];
            float4 w1 = *(const float4*)&Wk[tx * 8 + 4];
            u64 bp[4] = {pack2(w0.x, w0.y), pack2(w0.z, w0.w),
                         pack2(w1.x, w1.y), pack2(w1.z, w1.w)};
            float ar[8] = {a0.x, a0.y, a0.z, a0.w, a1.x, a1.y, a1.z, a1.w};
#pragma unroll
            for (int r = 0; r < 8; r++) {
                u64 ab = pack2(ar[r], ar[r]);
#pragma unroll
                for (int cp = 0; cp < 4; cp++) acc[r][cp] = fma2(ab, bp[cp], acc[r][cp]);
            }
        }
    }
#pragma unroll
    for (int r = 0; r < 8; r++) {
        float v[8];
#pragma unroll
        for (int cp = 0; cp < 4; cp++) {
            float x, y;
            unpack2(acc[r][cp], x, y);
            v[2 * cp]     = fmaxf(x + sb[tx * 8 + 2 * cp], 0.f);
            v[2 * cp + 1] = fmaxf(y + sb[tx * 8 + 2 * cp + 1], 0.f);
        }
        float* o = &g_h[(size_t)(n0 + ty * 8 + r) * HIDF + tx * 8];
        *(float4*)&o[0] = make_float4(v[0], v[1], v[2], v[3]);
        *(float4*)&o[4] = make_float4(v[4], v[5], v[6], v[7]);
    }
}

// ---------------- GEMM-P: p = (h*rs_out) @ [W2|W3]  [65536x128]@[128x64] --
__global__ __launch_bounds__(256, 2) void k_gemm_p(const float* __restrict__ W2,
                                                   const float* __restrict__ W3) {
    __shared__ __align__(16) float sA[32 * 132];
    __shared__ __align__(16) float sW[32 * 64];
    int tid = threadIdx.x;
    int n0 = blockIdx.x * 128;
    int tx = tid & 15, ty = tid >> 4;

    u64 acc[8][2];
#pragma unroll
    for (int r = 0; r < 8; r++) { acc[r][0] = 0ull; acc[r][1] = 0ull; }

    for (int kc = 0; kc < 4; kc++) {
        __syncthreads();
#pragma unroll
        for (int it = 0; it < 4; it++) {
            int idx = it * 256 + tid;              // float4 idx, 1024 total
            int r = idx >> 3, k4 = (idx & 7) * 4;
            float rs = g_rs_out[n0 + r];
            float4 v = *(const float4*)&g_h[(size_t)(n0 + r) * HIDF + kc * 32 + k4];
            sA[(k4 + 0) * 132 + r] = v.x * rs;
            sA[(k4 + 1) * 132 + r] = v.y * rs;
            sA[(k4 + 2) * 132 + r] = v.z * rs;
            sA[(k4 + 3) * 132 + r] = v.w * rs;
        }
        {
            int idx = tid;                          // float4 idx, 512 total
            for (int it = 0; it < 2; it++, idx += 256) {
                int k = idx >> 4, c4 = (idx & 15) * 4;
                int kr = kc * 32 + k;
                float4 v;
                if (c4 < 32) v = *(const float4*)&W2[kr * 32 + c4];
                else         v = *(const float4*)&W3[kr * 32 + (c4 - 32)];
                *(float4*)&sW[k * 64 + c4] = v;
            }
        }
        __syncthreads();
#pragma unroll 4
        for (int k = 0; k < 32; k++) {
            const float* Ak = &sA[k * 132];
            const float* Wk = &sW[k * 64];
            float4 a0 = *(const float4*)&Ak[ty * 8];
            float4 a1 = *(const float4*)&Ak[ty * 8 + 4];
            float4 w0 = *(const float4*)&Wk[tx * 4];
            u64 bp[2] = {pack2(w0.x, w0.y), pack2(w0.z, w0.w)};
            float ar[8] = {a0.x, a0.y, a0.z, a0.w, a1.x, a1.y, a1.z, a1.w};
#pragma unroll
            for (int r = 0; r < 8; r++) {
                u64 ab = pack2(ar[r], ar[r]);
                acc[r][0] = fma2(ab, bp[0], acc[r][0]);
                acc[r][1] = fma2(ab, bp[1], acc[r][1]);
            }
        }
    }
#pragma unroll
    for (int r = 0; r < 8; r++) {
        float v[4];
        unpack2(acc[r][0], v[0], v[1]);
        unpack2(acc[r][1], v[2], v[3]);
        *(float4*)&g_p[(size_t)(n0 + ty * 8 + r) * 64 + tx * 4] =
            make_float4(v[0], v[1], v[2], v[3]);
    }
}

// ---------------- adj = sigmoid(Z Z^T): upper-tri tiles + mirrored write --
__global__ __launch_bounds__(256, 2) void k_adj(float* __restrict__ out) {
    __shared__ __align__(16) float sA[32 * 132];
    __shared__ __align__(16) float sB[32 * 132];

    int g = blockIdx.y;
    int t = blockIdx.x, bi = 0;
    while (t >= 8 - bi) { t -= 8 - bi; bi++; }
    int bj = bi + t;
    int i0 = bi * 128, j0 = bj * 128;

    const float4* zA4 = (const float4*)(g_z + ((size_t)(g * NPG + i0)) * OUTF);
    const float4* zB4 = (const float4*)(g_z + ((size_t)(g * NPG + j0)) * OUTF);
    int tid = threadIdx.x;

#pragma unroll
    for (int it = 0; it < 4; it++) {
        int idx = it * 256 + tid;                  // float4 idx, 1024 total
        int r = idx >> 3, k4 = (idx & 7) * 4;
        float4 va = zA4[idx];
        float4 vb = zB4[idx];
        sA[(k4 + 0) * 132 + r] = va.x;
        sA[(k4 + 1) * 132 + r] = va.y;
        sA[(k4 + 2) * 132 + r] = va.z;
        sA[(k4 + 3) * 132 + r] = va.w;
        sB[(k4 + 0) * 132 + r] = vb.x;
        sB[(k4 + 1) * 132 + r] = vb.y;
        sB[(k4 + 2) * 132 + r] = vb.z;
        sB[(k4 + 3) * 132 + r] = vb.w;
    }
    __syncthreads();

    int tx = tid & 15, ty = tid >> 4;
    u64 acc[8][4];
#pragma unroll
    for (int r = 0; r < 8; r++)
#pragma unroll
        for (int cp = 0; cp < 4; cp++) acc[r][cp] = 0ull;

#pragma unroll 4
    for (int k = 0; k < 32; k++) {
        const float* Ak = &sA[k * 132];
        const float* Bk = &sB[k * 132];
        float4 a0 = *(const float4*)&Ak[ty * 8];
        float4 a1 = *(const float4*)&Ak[ty * 8 + 4];
        float4 b0 = *(const float4*)&Bk[tx * 8];
        float4 b1 = *(const float4*)&Bk[tx * 8 + 4];
        u64 bp[4] = {pack2(b0.x, b0.y), pack2(b0.z, b0.w),
                     pack2(b1.x, b1.y), pack2(b1.z, b1.w)};
        float ar[8] = {a0.x, a0.y, a0.z, a0.w, a1.x, a1.y, a1.z, a1.w};
#pragma unroll
        for (int r = 0; r < 8; r++) {
            u64 ab = pack2(ar[r], ar[r]);
#pragma unroll
            for (int cp = 0; cp < 4; cp++) acc[r][cp] = fma2(ab, bp[cp], acc[r][cp]);
        }
    }

    float m[8][8];
#pragma unroll
    for (int r = 0; r < 8; r++)
#pragma unroll
        for (int cp = 0; cp < 4; cp++) {
            float x, y;
            unpack2(acc[r][cp], x, y);
            m[r][2 * cp]     = sigm(x);
            m[r][2 * cp + 1] = sigm(y);
        }

    float* ob = out + ((size_t)(g * NPG + i0)) * NPG + j0;
#pragma unroll
    for (int r = 0; r < 8; r++) {
        float* o = &ob[(size_t)(ty * 8 + r) * NPG + tx * 8];
        *(float4*)&o[0] = make_float4(m[r][0], m[r][1], m[r][2], m[r][3]);
        *(float4*)&o[4] = make_float4(m[r][4], m[r][5], m[r][6], m[r][7]);
    }
    if (bi != bj) {
        float* obT = out + ((size_t)(g * NPG + j0)) * NPG + i0;
#pragma unroll
        for (int c = 0; c < 8; c++) {
            float* o = &obT[(size_t)(tx * 8 + c) * NPG + ty * 8];
            *(float4*)&o[0] = make_float4(m[0][c], m[1][c], m[2][c], m[3][c]);
            *(float4*)&o[4] = make_float4(m[4][c], m[5][c], m[6][c], m[7][c]);
        }
    }
}

// ---------------- launch ---------------------------------------------------
extern "C" void kernel_launch(void* const* d_in, const int* in_sizes, int n_in,
                              void* d_out, int out_size) {
    const float* features = (const float*)d_in[0];
    const int*   src      = (const int*)d_in[1];
    const int*   dst      = (const int*)d_in[2];
    const float* noise    = (const float*)d_in[3];
    const float* W1       = (const float*)d_in[4];
    const float* b1       = (const float*)d_in[5];
    const float* W2       = (const float*)d_in[6];
    const float* b2       = (const float*)d_in[7];
    const float* W3       = (const float*)d_in[8];
    const float* b3       = (const float*)d_in[9];

    float* out      = (float*)d_out;
    float* out_adj  = out;
    float* out_mean = out + MEAN_OFF;
    float* out_ls   = out + LS_OFF;

    static int smem_set = 0;
    if (!smem_set) {
        cudaFuncSetAttribute(k_agg1s, cudaFuncAttributeMaxDynamicSharedMemorySize, AGG_SMEM);
        cudaFuncSetAttribute(k_agg2s, cudaFuncAttributeMaxDynamicSharedMemorySize, AGG_SMEM);
        smem_set = 1;
    }

    k_build<<<BB, 1024>>>(src, dst);
    k_agg1s<<<dim3(BB, 2), 1024, AGG_SMEM>>>(features);
    k_gemm1<<<512, 256>>>(W1, b1);
    k_gemm_p<<<512, 256>>>(W2, W3);
    k_agg2s<<<dim3(BB, 2), 1024, AGG_SMEM>>>();
    k_z<<<NN * 32 / 256, 256>>>(noise, b2, b3, out_mean, out_ls);
    k_adj<<<dim3(36, BB), 256>>>(out_adj);
}